// round 3
// baseline (speedup 1.0000x reference)
#include <cuda_runtime.h>
#include <math.h>

// Problem constants (fixed by setup_inputs)
#define BATCH   8
#define CHAN    256
#define NPIX    16384        // 128*128
#define NITER   16
#define TILE    64           // pixels per tile -> 64 KB smem/block, 3 blocks/SM
#define NTHR    256
#define NT      (NPIX/TILE)  // 256 tiles per batch

// d_out layout: reprVecs [16,8,256] | sims [16,8,16384] | selpos [8,16384]
#define OFF_SIMS   (NITER*BATCH*CHAN)
#define OFF_SELPOS (OFF_SIMS + NITER*BATCH*NPIX)

// Scratch (__device__ globals; allocations forbidden)
__device__ float g_score[BATCH*NPIX];
__device__ float g_accum[BATCH*CHAN];
__device__ float g_sumsim[BATCH];
__device__ float g_rv[BATCH*CHAN];
__device__ float g_cand_val[BATCH*NT];
__device__ int   g_cand_idx[BATCH*NT];

// ---------------------------------------------------------------------------
__global__ void init_kernel(float* __restrict__ selpos) {
    int i = blockIdx.x * blockDim.x + threadIdx.x;
    if (i < BATCH*NPIX) selpos[i] = 0.0f;
    if (i < BATCH*CHAN) g_accum[i] = 0.0f;
    if (i < BATCH)      g_sumsim[i] = 0.0f;
}

// ---------------------------------------------------------------------------
// One block per batch. (a) epilogue of iter-1 (normalize repr), (b) pick index
// for iter (reduce 256 per-tile candidates, or N/2 at iter 0), (c) selpos,
// (d) gather representative vector into g_rv. iter==NITER: epilogue only.
__global__ void select_kernel(int iter, const float* __restrict__ x,
                              float* __restrict__ repr_out,
                              float* __restrict__ selpos) {
    const int b   = blockIdx.x;
    const int tid = threadIdx.x;
    __shared__ float s_val[NTHR];
    __shared__ int   s_idx[NTHR];
    __shared__ int   s_ind;

    if (iter > 0) {
        float inv = 1.0f / g_sumsim[b];
        repr_out[((size_t)(iter-1)*BATCH + b)*CHAN + tid] =
            g_accum[b*CHAN + tid] * inv;
        g_accum[b*CHAN + tid] = 0.0f;
    }
    if (iter >= NITER) return;

    if (iter == 0) {
        if (tid == 0) s_ind = NPIX / 2;
        __syncthreads();
    } else {
        // reduce NT=256 per-tile candidates; ties -> lowest index (jnp.argmax)
        s_val[tid] = g_cand_val[b*NT + tid];
        s_idx[tid] = g_cand_idx[b*NT + tid];
        __syncthreads();
        for (int s = NTHR/2; s > 0; s >>= 1) {
            if (tid < s) {
                float v2 = s_val[tid+s]; int i2 = s_idx[tid+s];
                if (v2 > s_val[tid] || (v2 == s_val[tid] && i2 < s_idx[tid])) {
                    s_val[tid] = v2; s_idx[tid] = i2;
                }
            }
            __syncthreads();
        }
        if (tid == 0) s_ind = s_idx[0];
        __syncthreads();
    }
    const int ind = s_ind;
    if (tid == 0) {
        selpos[(size_t)b * NPIX + ind] += 1.0f;
        g_sumsim[b] = 0.0f;
    }
    // gather representative vector (strided, L2-served)
    g_rv[b*CHAN + tid] = x[((size_t)b*CHAN + tid)*NPIX + ind];
}

// ---------------------------------------------------------------------------
// Main kernel: one block per (64-pixel tile, batch) = 2048 blocks.
// Stages [256 c x 64 n] fp32 (64 KB) in SMEM; distance pass and sim-weighted
// channel reduction both read SMEM -> exactly one HBM read of x per iter.
// 3 blocks/SM co-resident -> staging of one block overlaps compute of others.
extern "C" __global__ void __launch_bounds__(NTHR, 3)
main_kernel(int iter, const float* __restrict__ x,
            float* __restrict__ sims_out)
{
    extern __shared__ float xs[];              // [CHAN][TILE] = 64 KB
    __shared__ float s_rv[CHAN];
    __shared__ float s_sim[TILE];
    __shared__ float s_part[NTHR];
    __shared__ float s_red[4];
    __shared__ int   s_redi[2];
    __shared__ float s_redv[2];

    const int b    = blockIdx.y;
    const int tile = blockIdx.x;
    const int n0   = tile * TILE;
    const int tid  = threadIdx.x;
    const int lane = tid & 31;
    const int w    = tid >> 5;
    const float* __restrict__ xb = x + (size_t)b * CHAN * NPIX;

    s_rv[tid] = g_rv[b*CHAN + tid];

    // ---- stage tile: 4096 float4 loads, coalesced, high MLP ----
    #pragma unroll
    for (int i = 0; i < 16; ++i) {
        int idx4 = tid + i * NTHR;             // 0..4095
        int c    = idx4 >> 4;                  // channel
        int k    = idx4 & 15;                  // float4 within row
        ((float4*)xs)[idx4] =
            *(const float4*)(xb + (size_t)c * NPIX + n0 + k * 4);
    }
    __syncthreads();

    // ---- distance: 4 threads per pixel, 64 channels each ----
    {
        const int n = tid & 63;
        const int q = tid >> 6;
        float acc = 0.0f;
        #pragma unroll 8
        for (int c = q * 64; c < q * 64 + 64; ++c) {
            float d = xs[c * TILE + n] - s_rv[c];
            acc = fmaf(d, d, acc);
        }
        s_part[tid] = acc;
    }
    __syncthreads();

    // ---- sim, score update, per-tile argmax candidate (warps 0,1) ----
    if (tid < TILE) {
        float ssq = s_part[tid] + s_part[tid + 64] +
                    s_part[tid + 128] + s_part[tid + 192];
        float d   = sqrtf(ssq + 1e-12f);
        float sim = __expf(-0.05f * d);
        s_sim[tid] = sim;
        const int np = n0 + tid;
        sims_out[((size_t)iter * BATCH + b) * NPIX + np] = sim;
        float sc = 1.0f - sim;
        if (iter > 0) sc *= g_score[(size_t)b * NPIX + np];
        g_score[(size_t)b * NPIX + np] = sc;

        // sim-sum within the two active warps
        float ws = sim;
        #pragma unroll
        for (int o = 16; o; o >>= 1) ws += __shfl_down_sync(0xffffffffu, ws, o);
        if (lane == 0) s_red[w] = ws;

        // warp argmax of sc (ascending index within warp -> lowest-index ties)
        float bv = sc; int bi = np;
        #pragma unroll
        for (int o = 16; o; o >>= 1) {
            float v2 = __shfl_down_sync(0xffffffffu, bv, o);
            int   i2 = __shfl_down_sync(0xffffffffu, bi, o);
            if (v2 > bv || (v2 == bv && i2 < bi)) { bv = v2; bi = i2; }
        }
        if (lane == 0) { s_redv[w] = bv; s_redi[w] = bi; }
    }
    __syncthreads();
    if (tid == 0) {
        atomicAdd(&g_sumsim[b], s_red[0] + s_red[1]);
        float v0 = s_redv[0], v1 = s_redv[1];
        int   i0 = s_redi[0], i1 = s_redi[1];
        bool take1 = (v1 > v0) || (v1 == v0 && i1 < i0);
        g_cand_val[b*NT + tile] = take1 ? v1 : v0;
        g_cand_idx[b*NT + tile] = take1 ? i1 : i0;
    }

    // ---- repr accumulation: warp w owns channels [32w, 32w+32) ----
    {
        float sa = s_sim[lane];
        float sb = s_sim[lane + 32];
        #pragma unroll
        for (int ci = 0; ci < 32; ++ci) {
            const int c = w * 32 + ci;
            float a = fmaf(sa, xs[c * TILE + lane],
                      sb * xs[c * TILE + lane + 32]);
            #pragma unroll
            for (int o = 16; o; o >>= 1)
                a += __shfl_down_sync(0xffffffffu, a, o);
            if (lane == 0) atomicAdd(&g_accum[b * CHAN + c], a);
        }
    }
}

// ---------------------------------------------------------------------------
extern "C" void kernel_launch(void* const* d_in, const int* in_sizes, int n_in,
                              void* d_out, int out_size) {
    const float* x = (const float*)d_in[0];
    float* out      = (float*)d_out;
    float* repr_out = out;
    float* sims_out = out + OFF_SIMS;
    float* selpos   = out + OFF_SELPOS;

    cudaFuncSetAttribute(main_kernel,
                         cudaFuncAttributeMaxDynamicSharedMemorySize,
                         CHAN * TILE * (int)sizeof(float));

    init_kernel<<<(BATCH*NPIX + NTHR - 1) / NTHR, NTHR>>>(selpos);

    dim3 grid(NT, BATCH);
    for (int i = 0; i < NITER; ++i) {
        select_kernel<<<BATCH, NTHR>>>(i, x, repr_out, selpos);
        main_kernel<<<grid, NTHR, CHAN * TILE * sizeof(float)>>>(i, x, sims_out);
    }
    select_kernel<<<BATCH, NTHR>>>(NITER, x, repr_out, selpos);
}

// round 5
// speedup vs baseline: 2.5455x; 2.5455x over previous
#include <cuda_runtime.h>
#include <math.h>

// Problem constants (fixed by setup_inputs)
#define BATCH   8
#define CHAN    256
#define NPIX    16384        // 128*128
#define NITER   16
#define TILE    64           // pixels per tile
#define STRIDE  65           // smem row stride (conflict-free channel walk)
#define NTHR    256
#define NT      (NPIX/TILE)  // 256 tiles per batch

// d_out layout: reprVecs [16,8,256] | sims [16,8,16384] | selpos [8,16384]
#define OFF_SIMS   (NITER*BATCH*CHAN)
#define OFF_SELPOS (OFF_SIMS + NITER*BATCH*NPIX)

// Scratch (__device__ globals; allocations forbidden)
__device__ float g_score[BATCH*NPIX];
__device__ float g_rv[BATCH*CHAN];
__device__ float g_cand_val[BATCH*NT];
__device__ int   g_cand_idx[BATCH*NT];
// per-(iter,batch,tile) partials, reduced once at the end (off critical path)
__device__ float g_rpart[NITER*BATCH*NT*CHAN];   // 32 MB
__device__ float g_spart[NITER*BATCH*NT];        // 512 KB

// ---------------------------------------------------------------------------
// One block per batch: reduce NT per-tile argmax candidates (or pick N/2 at
// iter 0), bump selpos, gather the representative vector into g_rv.
__global__ void select_kernel(int iter, const float* __restrict__ x,
                              float* __restrict__ selpos) {
    const int b   = blockIdx.x;
    const int tid = threadIdx.x;
    __shared__ float s_val[NTHR];
    __shared__ int   s_idx[NTHR];
    __shared__ int   s_ind;

    if (iter == 0) {
        // zero my batch's selpos slice (output is poisoned before timing)
        for (int k = tid; k < NPIX; k += NTHR)
            selpos[(size_t)b * NPIX + k] = 0.0f;
        if (tid == 0) s_ind = NPIX / 2;
        __syncthreads();
    } else {
        // reduce NT=256 per-tile candidates; ties -> lowest index (jnp.argmax)
        s_val[tid] = g_cand_val[b*NT + tid];
        s_idx[tid] = g_cand_idx[b*NT + tid];
        __syncthreads();
        for (int s = NTHR/2; s > 0; s >>= 1) {
            if (tid < s) {
                float v2 = s_val[tid+s]; int i2 = s_idx[tid+s];
                if (v2 > s_val[tid] || (v2 == s_val[tid] && i2 < s_idx[tid])) {
                    s_val[tid] = v2; s_idx[tid] = i2;
                }
            }
            __syncthreads();
        }
        if (tid == 0) s_ind = s_idx[0];
        __syncthreads();
    }
    const int ind = s_ind;
    if (tid == 0) selpos[(size_t)b * NPIX + ind] += 1.0f;
    // gather representative vector (256 independent strided loads, high MLP)
    g_rv[b*CHAN + tid] = x[((size_t)b*CHAN + tid)*NPIX + ind];
}

// ---------------------------------------------------------------------------
// Main kernel: one block per (64-pixel tile, batch) = 2048 blocks, 3/SM.
// SMEM tile layout [c][n] with row stride 65. Distance pass + repr pass both
// read SMEM; repr pass is thread-per-channel (no shuffles, no atomics) and
// writes per-tile partials to scratch.
extern "C" __global__ void __launch_bounds__(NTHR, 3)
main_kernel(int iter, const float* __restrict__ x,
            float* __restrict__ sims_out)
{
    extern __shared__ float xs[];              // CHAN*STRIDE floats = 66.6 KB
    __shared__ float s_rv[CHAN];
    __shared__ float s_sim[TILE];
    __shared__ float s_part[NTHR];
    __shared__ float s_red[2];
    __shared__ int   s_redi[2];
    __shared__ float s_redv[2];

    const int b    = blockIdx.y;
    const int tile = blockIdx.x;
    const int n0   = tile * TILE;
    const int tid  = threadIdx.x;
    const int lane = tid & 31;
    const int w    = tid >> 5;
    const float* __restrict__ xb = x + (size_t)b * CHAN * NPIX;

    s_rv[tid] = g_rv[b*CHAN + tid];

    // ---- stage tile: float4 gmem loads (coalesced), scalar smem stores ----
    #pragma unroll
    for (int i = 0; i < 16; ++i) {
        int idx4 = tid + i * NTHR;             // 0..4095
        int c    = idx4 >> 4;                  // channel
        int k    = (idx4 & 15) * 4;            // float offset in row
        float4 v = *(const float4*)(xb + (size_t)c * NPIX + n0 + k);
        float* d = xs + c * STRIDE + k;
        d[0] = v.x; d[1] = v.y; d[2] = v.z; d[3] = v.w;
    }
    __syncthreads();

    // ---- distance: 4 threads per pixel, 64 channels each ----
    {
        const int n = tid & 63;
        const int q = tid >> 6;
        float a0 = 0.f, a1 = 0.f, a2 = 0.f, a3 = 0.f;
        const int cb = q * 64;
        #pragma unroll
        for (int c = 0; c < 64; c += 4) {
            float d0 = xs[(cb+c  ) * STRIDE + n] - s_rv[cb+c  ];
            float d1 = xs[(cb+c+1) * STRIDE + n] - s_rv[cb+c+1];
            float d2 = xs[(cb+c+2) * STRIDE + n] - s_rv[cb+c+2];
            float d3 = xs[(cb+c+3) * STRIDE + n] - s_rv[cb+c+3];
            a0 = fmaf(d0, d0, a0); a1 = fmaf(d1, d1, a1);
            a2 = fmaf(d2, d2, a2); a3 = fmaf(d3, d3, a3);
        }
        s_part[tid] = (a0 + a1) + (a2 + a3);
    }
    __syncthreads();

    // ---- sim, score update, per-tile sumsim + argmax candidate ----
    if (tid < TILE) {
        float ssq = s_part[tid] + s_part[tid + 64] +
                    s_part[tid + 128] + s_part[tid + 192];
        float d   = sqrtf(ssq + 1e-12f);
        float sim = __expf(-0.05f * d);
        s_sim[tid] = sim;
        const int np = n0 + tid;
        sims_out[((size_t)iter * BATCH + b) * NPIX + np] = sim;
        float sc = 1.0f - sim;
        if (iter > 0) sc *= g_score[(size_t)b * NPIX + np];
        g_score[(size_t)b * NPIX + np] = sc;

        float ws = sim;
        #pragma unroll
        for (int o = 16; o; o >>= 1) ws += __shfl_down_sync(0xffffffffu, ws, o);
        if (lane == 0) s_red[w] = ws;

        float bv = sc; int bi = np;
        #pragma unroll
        for (int o = 16; o; o >>= 1) {
            float v2 = __shfl_down_sync(0xffffffffu, bv, o);
            int   i2 = __shfl_down_sync(0xffffffffu, bi, o);
            if (v2 > bv || (v2 == bv && i2 < bi)) { bv = v2; bi = i2; }
        }
        if (lane == 0) { s_redv[w] = bv; s_redi[w] = bi; }
    }
    __syncthreads();
    if (tid == 0) {
        g_spart[((size_t)iter * BATCH + b) * NT + tile] = s_red[0] + s_red[1];
        float v0 = s_redv[0], v1 = s_redv[1];
        int   i0 = s_redi[0], i1 = s_redi[1];
        bool take1 = (v1 > v0) || (v1 == v0 && i1 < i0);
        g_cand_val[b*NT + tile] = take1 ? v1 : v0;
        g_cand_idx[b*NT + tile] = take1 ? i1 : i0;
    }

    // ---- repr accumulation: thread tid owns channel tid (conflict-free) ----
    {
        const float* row = xs + tid * STRIDE;
        float a0 = 0.f, a1 = 0.f, a2 = 0.f, a3 = 0.f;
        #pragma unroll
        for (int n = 0; n < TILE; n += 4) {
            a0 = fmaf(s_sim[n  ], row[n  ], a0);
            a1 = fmaf(s_sim[n+1], row[n+1], a1);
            a2 = fmaf(s_sim[n+2], row[n+2], a2);
            a3 = fmaf(s_sim[n+3], row[n+3], a3);
        }
        g_rpart[(((size_t)iter * BATCH + b) * NT + tile) * CHAN + tid] =
            (a0 + a1) + (a2 + a3);
    }
}

// ---------------------------------------------------------------------------
// Final reduction: one block per (iter, batch). Sum 256 tile partials per
// channel, normalize by total sim-sum, write reprVecs.
__global__ void final_kernel(float* __restrict__ repr_out) {
    const int blk = blockIdx.x;                // it*BATCH + b
    const int tid = threadIdx.x;
    __shared__ float s_sp[NTHR];

    // total sim-sum for this (iter, batch)
    s_sp[tid] = g_spart[(size_t)blk * NT + tid];
    __syncthreads();
    for (int s = NTHR/2; s > 0; s >>= 1) {
        if (tid < s) s_sp[tid] += s_sp[tid + s];
        __syncthreads();
    }
    const float inv = 1.0f / s_sp[0];

    // channel tid: sum over 256 tiles (coalesced across tid)
    const float* rp = g_rpart + (size_t)blk * NT * CHAN;
    float a0 = 0.f, a1 = 0.f, a2 = 0.f, a3 = 0.f;
    #pragma unroll 4
    for (int t = 0; t < NT; t += 4) {
        a0 += rp[(t  ) * CHAN + tid];
        a1 += rp[(t+1) * CHAN + tid];
        a2 += rp[(t+2) * CHAN + tid];
        a3 += rp[(t+3) * CHAN + tid];
    }
    repr_out[(size_t)blk * CHAN + tid] = ((a0 + a1) + (a2 + a3)) * inv;
}

// ---------------------------------------------------------------------------
extern "C" void kernel_launch(void* const* d_in, const int* in_sizes, int n_in,
                              void* d_out, int out_size) {
    const float* x = (const float*)d_in[0];
    float* out      = (float*)d_out;
    float* repr_out = out;
    float* sims_out = out + OFF_SIMS;
    float* selpos   = out + OFF_SELPOS;

    cudaFuncSetAttribute(main_kernel,
                         cudaFuncAttributeMaxDynamicSharedMemorySize,
                         CHAN * STRIDE * (int)sizeof(float));

    dim3 grid(NT, BATCH);
    for (int i = 0; i < NITER; ++i) {
        select_kernel<<<BATCH, NTHR>>>(i, x, selpos);
        main_kernel<<<grid, NTHR, CHAN * STRIDE * sizeof(float)>>>(i, x, sims_out);
    }
    final_kernel<<<NITER * BATCH, NTHR>>>(repr_out);
}